// round 6
// baseline (speedup 1.0000x reference)
#include <cuda_runtime.h>
#include <cuda_fp16.h>
#include <stdint.h>

#define O_DIM 4096
#define I_DIM 4096
#define B_DIM 4096

#if defined(__CUDA_ARCH_SPECIFIC__) || defined(__CUDA_ARCH_FEAT_SM103_ALL) || defined(__CUDA_ARCH_FEAT_SM100_ALL)
#define HAS_TC 1
#else
#define HAS_TC 0
#endif

// -------- scratch (static device globals; allocation-free) --------
__device__ __half g_Xh [(size_t)B_DIM * I_DIM];
__device__ __half g_X2h[(size_t)B_DIM * I_DIM];   // used by fallback path only
__device__ __half g_Wm [(size_t)O_DIM * I_DIM];
__device__ __half g_Wv [(size_t)O_DIM * I_DIM];
__device__ int    g_use_tc;

__global__ void probe_kernel() {
#if HAS_TC
    g_use_tc = 1;
#else
    g_use_tc = 0;
#endif
}

// -------- prep kernels (HBM-bound) --------
__global__ void prep_x_kernel(const float4* __restrict__ x, int n4) {
    int i = blockIdx.x * blockDim.x + threadIdx.x;
    if (i >= n4) return;
    float4 v = x[i];
    __half2* xh = reinterpret_cast<__half2*>(g_Xh);
    __half2* x2 = reinterpret_cast<__half2*>(g_X2h);
    xh[2*i]   = __floats2half2_rn(v.x, v.y);
    xh[2*i+1] = __floats2half2_rn(v.z, v.w);
    x2[2*i]   = __floats2half2_rn(v.x*v.x, v.y*v.y);
    x2[2*i+1] = __floats2half2_rn(v.z*v.z, v.w*v.w);
}

__global__ void prep_w_kernel(const float4* __restrict__ tn4,
                              const float4* __restrict__ tp4,
                              const float4* __restrict__ sc4, int n4) {
    int i = blockIdx.x * blockDim.x + threadIdx.x;
    if (i >= n4) return;
    float4 a = tn4[i], b = tp4[i], s = sc4[i];
    const float* ap = &a.x;
    const float* bp = &b.x;
    const float* sp = &s.x;
    float wm[4], wv[4];
#pragma unroll
    for (int c = 0; c < 4; c++) {
        float t_n = ap[c], t_p = bp[c], sc = sp[c];
        float m  = fmaxf(fmaxf(t_n, t_p), 0.0f);
        float en = __expf(t_n - m);
        float ez = __expf(-m);
        float ep = __expf(t_p - m);
        float inv = 1.0f / (en + ez + ep);
        float pn = en * inv, pp = ep * inv;
        float d  = pp - pn;
        wm[c] = d * sc;
        wv[c] = (pp + pn - d * d) * sc * sc;
    }
    __half2* wmh = reinterpret_cast<__half2*>(g_Wm);
    __half2* wvh = reinterpret_cast<__half2*>(g_Wv);
    wmh[2*i]   = __floats2half2_rn(wm[0], wm[1]);
    wmh[2*i+1] = __floats2half2_rn(wm[2], wm[3]);
    wvh[2*i]   = __floats2half2_rn(wv[0], wv[1]);
    wvh[2*i+1] = __floats2half2_rn(wv[2], wv[3]);
}

// ======================= common helpers =======================
__device__ __forceinline__ uint32_t smem_u32(const void* p) {
    uint32_t a;
    asm("{ .reg .u64 t; cvta.to.shared.u64 t, %1; cvt.u32.u64 %0, t; }"
        : "=r"(a) : "l"(p));
    return a;
}
__device__ __forceinline__ uint32_t swz(uint32_t o) { return o ^ ((o >> 3) & 0x70); }

__device__ __forceinline__ void cpasync16(uint32_t d, const void* s) {
    asm volatile("cp.async.cg.shared.global [%0], [%1], 16;\n" :: "r"(d), "l"(s));
}
#define CP_COMMIT() asm volatile("cp.async.commit_group;\n" ::: "memory")

__device__ __forceinline__ void lds128(uint32_t& a, uint32_t& b, uint32_t& c,
                                       uint32_t& d, uint32_t addr) {
    asm volatile("ld.shared.v4.u32 {%0,%1,%2,%3}, [%4];"
                 : "=r"(a), "=r"(b), "=r"(c), "=r"(d) : "r"(addr));
}
__device__ __forceinline__ void sts128(uint32_t addr, uint32_t a, uint32_t b,
                                       uint32_t c, uint32_t d) {
    asm volatile("st.shared.v4.b32 [%0], {%1,%2,%3,%4};"
                 :: "r"(addr), "r"(a), "r"(b), "r"(c), "r"(d));
}
__device__ __forceinline__ uint32_t sqh2(uint32_t v) {
    __half2 h = *reinterpret_cast<__half2*>(&v);
    h = __hmul2(h, h);
    return *reinterpret_cast<uint32_t*>(&h);
}

// ======================= cg2 tcgen05 dual-GEMM, warp-specialized =======================
// X2 tile is computed in smem from X (warps 0-1); only X, Wm, Wv hit L2.
#define TILE_MH 128
#define TILE_N  256
#define KB      64
#define SX      0
#define SX2     16384
#define SWM     32768
#define SWV     49152
#define STAGE_BYTES 65536
#define NSTAGE  3
#define TC_SMEM (NSTAGE * STAGE_BYTES + 1024)
#define TC_THREADS 160

#define MMA_IDESC ((1u << 4) | ((TILE_N / 8) << 17) | ((256 / 16) << 24))

#if HAS_TC
__device__ __forceinline__ uint64_t make_desc(uint32_t addr) {
    const uint64_t base =
        (uint64_t(2) << 61) | (uint64_t(1) << 46) |
        (uint64_t(64) << 32) | (uint64_t(1) << 16);
    return base | ((uint64_t)(addr >> 4) & 0x3FFF);
}

__device__ __forceinline__ void mma_f16_ss_cg2(uint32_t d_tmem, uint64_t a_desc,
                                               uint64_t b_desc, uint32_t idesc,
                                               uint32_t acc) {
    asm volatile(
        "{\n\t.reg .pred p;\n\t"
        "setp.ne.u32 p, %5, 0;\n\t"
        "tcgen05.mma.cta_group::2.kind::f16 [%0], %1, %2, %3, "
        "{%4, %4, %4, %4, %4, %4, %4, %4}, p;\n\t"
        "}"
        :: "r"(d_tmem), "l"(a_desc), "l"(b_desc), "r"(idesc), "r"(0u), "r"(acc)
        : "memory");
}

__device__ __forceinline__ void mbar_wait(uint32_t mbar, uint32_t parity) {
    asm volatile(
        "{\n\t.reg .pred P;\n\t"
        "WL_%=:\n\t"
        "mbarrier.try_wait.parity.acquire.cta.shared::cta.b64 P, [%0], %1, 0x989680;\n\t"
        "@P bra.uni WD_%=;\n\t"
        "bra.uni WL_%=;\n\t"
        "WD_%=:\n\t}"
        :: "r"(mbar), "r"(parity) : "memory");
}

__device__ __forceinline__ void mbar_arrive_rank(uint32_t local_addr, uint32_t rank) {
    asm volatile(
        "{\n\t.reg .b32 r;\n\t"
        "mapa.shared::cluster.u32 r, %0, %1;\n\t"
        "mbarrier.arrive.shared::cluster.b64 _, [r];\n\t"
        "}"
        :: "r"(local_addr), "r"(rank) : "memory");
}

#define MBAR_ARRIVE(mbar) \
    asm volatile("mbarrier.arrive.release.cta.shared::cta.b64 _, [%0];" :: "r"(mbar) : "memory")

#define CP_MBAR_ARRIVE_NOINC(mbar) \
    asm volatile("cp.async.mbarrier.arrive.noinc.shared::cta.b64 [%0];" \
                 :: "r"(mbar) : "memory")

#define TC_COMMIT_MC2(mbar) \
    asm volatile("tcgen05.commit.cta_group::2.mbarrier::arrive::one.shared::cluster.multicast::cluster.b64 [%0], %1;" \
                 :: "r"(mbar), "h"((uint16_t)3) : "memory")

#define TC_LD_X32(r, ta) \
    asm volatile( \
        "tcgen05.ld.sync.aligned.32x32b.x32.b32 " \
        "{%0, %1, %2, %3, %4, %5, %6, %7, %8, %9, %10, %11, %12, %13, %14, %15, " \
        " %16, %17, %18, %19, %20, %21, %22, %23, %24, %25, %26, %27, %28, %29, %30, %31}, [%32];" \
        : "=r"((r)[0]),  "=r"((r)[1]),  "=r"((r)[2]),  "=r"((r)[3]), \
          "=r"((r)[4]),  "=r"((r)[5]),  "=r"((r)[6]),  "=r"((r)[7]), \
          "=r"((r)[8]),  "=r"((r)[9]),  "=r"((r)[10]), "=r"((r)[11]), \
          "=r"((r)[12]), "=r"((r)[13]), "=r"((r)[14]), "=r"((r)[15]), \
          "=r"((r)[16]), "=r"((r)[17]), "=r"((r)[18]), "=r"((r)[19]), \
          "=r"((r)[20]), "=r"((r)[21]), "=r"((r)[22]), "=r"((r)[23]), \
          "=r"((r)[24]), "=r"((r)[25]), "=r"((r)[26]), "=r"((r)[27]), \
          "=r"((r)[28]), "=r"((r)[29]), "=r"((r)[30]), "=r"((r)[31]) \
        : "r"(ta))

#define CLUSTER_SYNC() do { \
    asm volatile("barrier.cluster.arrive.aligned;" ::: "memory"); \
    asm volatile("barrier.cluster.wait.aligned;" ::: "memory"); \
} while (0)
#endif  // HAS_TC

__global__ __launch_bounds__(TC_THREADS, 1) __cluster_dims__(2, 1, 1)
void lrnet_tc_kernel(const float* __restrict__ eps, float* __restrict__ out) {
#if HAS_TC
    extern __shared__ char dsm_raw[];
    // full[s] counts: leader 129 (64 X-thread arrives + 64 W cp-noinc + 1 peer fwd),
    //                 peer   128 (64 + 64).
    __shared__ __align__(16) unsigned long long s_full[NSTAGE];
    __shared__ __align__(16) unsigned long long s_done[NSTAGE];
    __shared__ uint32_t s_tmem;

    const int tid  = threadIdx.x;
    const int wid  = tid >> 5;
    const int lane = tid & 31;
    const int rank = blockIdx.x;
    const int bn   = blockIdx.y;
    const int bm   = blockIdx.z;

    uint32_t dyn  = smem_u32(dsm_raw);
    uint32_t base = (dyn + 1023u) & ~1023u;
    uint32_t fullA[NSTAGE], doneA[NSTAGE];
#pragma unroll
    for (int s = 0; s < NSTAGE; s++) {
        fullA[s] = smem_u32(&s_full[s]);
        doneA[s] = smem_u32(&s_done[s]);
    }

    if (wid == 0) {
        uint32_t slot = smem_u32(&s_tmem);
        asm volatile("tcgen05.alloc.cta_group::2.sync.aligned.shared::cta.b32 [%0], %1;"
                     :: "r"(slot), "r"(512u) : "memory");
        asm volatile("tcgen05.relinquish_alloc_permit.cta_group::2.sync.aligned;");
    }
    if (tid == 0) {
        const uint32_t fcnt = (rank == 0) ? 129u : 128u;
#pragma unroll
        for (int s = 0; s < NSTAGE; s++) {
            asm volatile("mbarrier.init.shared.b64 [%0], %1;" :: "r"(fullA[s]), "r"(fcnt) : "memory");
            asm volatile("mbarrier.init.shared.b64 [%0], %1;" :: "r"(doneA[s]), "r"(1u)   : "memory");
        }
    }
    __syncthreads();
    CLUSTER_SYNC();
    const uint32_t tmem = s_tmem;
    const int NK = I_DIM / KB;   // 64

    if (tid < 64) {
        // ------------- X producer + squarer: warps 0-1 -------------
        const size_t mrow0 = (size_t)bm * 256 + (size_t)rank * TILE_MH;
        for (int kt = 0; kt < NK; kt++) {
            const int s = kt % NSTAGE;
            if (kt >= NSTAGE)
                mbar_wait(doneA[s], (uint32_t)(((kt - NSTAGE) / NSTAGE) & 1));
            uint32_t sb = base + (uint32_t)s * STAGE_BYTES;
            size_t k0 = (size_t)kt * KB;
#pragma unroll
            for (int i = 0; i < 16; i++) {
                int idx = tid + i * 64;
                int row = idx >> 3, c = idx & 7;
                uint32_t off = swz((uint32_t)(row * 128 + c * 16));
                cpasync16(sb + SX + off, g_Xh + (mrow0 + row) * I_DIM + k0 + c * 8);
            }
            CP_COMMIT();
            asm volatile("cp.async.wait_group 0;\n" ::: "memory");  // my X chunks resident
#pragma unroll
            for (int i = 0; i < 16; i++) {
                int idx = tid + i * 64;
                int row = idx >> 3, c = idx & 7;
                uint32_t off = swz((uint32_t)(row * 128 + c * 16));
                uint32_t a0, a1, a2, a3;
                lds128(a0, a1, a2, a3, sb + SX + off);
                sts128(sb + SX2 + off, sqh2(a0), sqh2(a1), sqh2(a2), sqh2(a3));
            }
            asm volatile("fence.proxy.async.shared::cta;\n" ::: "memory");
            MBAR_ARRIVE(fullA[s]);
        }
    } else if (tid < 128) {
        // ------------- W producer: warps 2-3 (free-running) -------------
        const int t = tid - 64;
        const size_t nrow0 = (size_t)bn * TILE_N + (size_t)rank * 128;
        for (int kt = 0; kt < NK; kt++) {
            const int s = kt % NSTAGE;
            if (kt >= NSTAGE)
                mbar_wait(doneA[s], (uint32_t)(((kt - NSTAGE) / NSTAGE) & 1));
            uint32_t sb = base + (uint32_t)s * STAGE_BYTES;
            size_t k0 = (size_t)kt * KB;
#pragma unroll
            for (int i = 0; i < 16; i++) {
                int idx = t + i * 64;
                int row = idx >> 3, c = idx & 7;
                uint32_t off = swz((uint32_t)(row * 128 + c * 16));
                size_t gW = (nrow0 + row) * I_DIM + k0 + c * 8;
                cpasync16(sb + SWM + off, g_Wm + gW);
                cpasync16(sb + SWV + off, g_Wv + gW);
            }
            CP_MBAR_ARRIVE_NOINC(fullA[s]);
        }
    } else if (tid == 128) {
        if (rank == 0) {
            // ------------- MMA issuer (leader) -------------
            for (int kt = 0; kt < NK; kt++) {
                const int s = kt % NSTAGE;
                const uint32_t ph = (uint32_t)((kt / NSTAGE) & 1);
                mbar_wait(fullA[s], ph);
                asm volatile("fence.proxy.async.shared::cta;\n" ::: "memory");
                uint32_t sb = base + (uint32_t)s * STAGE_BYTES;
                uint64_t dx  = make_desc(sb + SX);
                uint64_t dx2 = make_desc(sb + SX2);
                uint64_t dwm = make_desc(sb + SWM);
                uint64_t dwv = make_desc(sb + SWV);
#pragma unroll
                for (int k = 0; k < 4; k++) {
                    uint32_t acc = (kt > 0 || k > 0) ? 1u : 0u;
                    mma_f16_ss_cg2(tmem,       dx  + k * 2, dwm + k * 2, MMA_IDESC, acc);
                    mma_f16_ss_cg2(tmem + 256, dx2 + k * 2, dwv + k * 2, MMA_IDESC, acc);
                }
                TC_COMMIT_MC2(doneA[s]);
            }
        } else {
            // ------------- full -> leader forwarder (peer) -------------
            for (int kt = 0; kt < NK; kt++) {
                const int s = kt % NSTAGE;
                const uint32_t ph = (uint32_t)((kt / NSTAGE) & 1);
                mbar_wait(fullA[s], ph);
                asm volatile("fence.proxy.async.shared::cta;\n" ::: "memory");
                mbar_arrive_rank(fullA[s], 0);
            }
        }
    }

    // ---- wait for final stage's MMAs, then fused epilogue ----
    if (tid < 128) {
        mbar_wait(doneA[(NK - 1) % NSTAGE], (uint32_t)(((NK - 1) / NSTAGE) & 1));
        asm volatile("tcgen05.fence::after_thread_sync;" ::: "memory");

        const size_t orow = (size_t)bm * 256 + (size_t)rank * TILE_MH + wid * 32 + lane;
#pragma unroll 1
        for (int c = 0; c < TILE_N / 32; c++) {
            uint32_t mu[32], va[32];
            TC_LD_X32(mu, tmem + c * 32);
            TC_LD_X32(va, tmem + 256 + c * 32);
            asm volatile("tcgen05.wait::ld.sync.aligned;" ::: "memory");
            size_t colb = (size_t)bn * TILE_N + c * 32;
            const float4* ep = (const float4*)(eps + orow * O_DIM + colb);
            float4*       op = (float4*)(out + orow * O_DIM + colb);
#pragma unroll
            for (int j = 0; j < 8; j++) {
                float4 e = ep[j];
                float4 o;
                o.x = __uint_as_float(mu[4*j+0]) + sqrtf(fmaxf(__uint_as_float(va[4*j+0]), 1e-8f)) * e.x;
                o.y = __uint_as_float(mu[4*j+1]) + sqrtf(fmaxf(__uint_as_float(va[4*j+1]), 1e-8f)) * e.y;
                o.z = __uint_as_float(mu[4*j+2]) + sqrtf(fmaxf(__uint_as_float(va[4*j+2]), 1e-8f)) * e.z;
                o.w = __uint_as_float(mu[4*j+3]) + sqrtf(fmaxf(__uint_as_float(va[4*j+3]), 1e-8f)) * e.w;
                op[j] = o;
            }
        }
        asm volatile("tcgen05.fence::before_thread_sync;" ::: "memory");
    }

    __syncthreads();
    if (wid == 0) {
        asm volatile("tcgen05.dealloc.cta_group::2.sync.aligned.b32 %0, %1;"
                     :: "r"(tmem), "r"(512u));
    }
    CLUSTER_SYNC();
#endif  // HAS_TC
}

// ======================= mma.sync fallback (plain sm_103) =======================
#define SM_STRIDE 40
#define MATH (128 * SM_STRIDE)
#define STAGEH (4 * MATH)
#define FB_SMEM (2 * STAGEH * (int)sizeof(__half))

#define MMA16816(dd, aa, bb) \
    asm volatile("mma.sync.aligned.m16n8k16.row.col.f32.f16.f16.f32 " \
                 "{%0,%1,%2,%3},{%4,%5,%6,%7},{%8,%9},{%0,%1,%2,%3};\n" \
                 : "+f"(dd[0]), "+f"(dd[1]), "+f"(dd[2]), "+f"(dd[3]) \
                 : "r"(aa[0]), "r"(aa[1]), "r"(aa[2]), "r"(aa[3]), \
                   "r"(bb[0]), "r"(bb[1]))

__global__ __launch_bounds__(256, 1)
void lrnet_gemm_kernel(const float* __restrict__ eps, float* __restrict__ out) {
    if (g_use_tc) return;
    extern __shared__ __half smem[];
    const int tid  = threadIdx.x;
    const int lane = tid & 31;
    const int wid  = tid >> 5;
    const int g    = lane >> 2;
    const int tg   = lane & 3;
    const int wm_  = wid & 3;
    const int wn_  = wid >> 2;
    const int bm   = blockIdx.y;
    const int bn   = blockIdx.x;

    float accm[2][8][4];
    float accv[2][8][4];
#pragma unroll
    for (int mt = 0; mt < 2; mt++)
#pragma unroll
        for (int nt = 0; nt < 8; nt++)
#pragma unroll
            for (int r = 0; r < 4; r++) { accm[mt][nt][r] = 0.f; accv[mt][nt][r] = 0.f; }

    const int row0A = bm * 128;
    const int row0W = bn * 128;

    auto load_stage = [&](int s, int kt) {
        const size_t k0 = (size_t)kt * 32;
        __half* basep = smem + (size_t)s * STAGEH;
#pragma unroll
        for (int c = 0; c < 2; c++) {
            int idx = tid + c * 256;
            int row = idx >> 2;
            int k8  = (idx & 3) * 8;
            size_t gA = (size_t)(row0A + row) * I_DIM + k0 + k8;
            size_t gW = (size_t)(row0W + row) * I_DIM + k0 + k8;
            int so = row * SM_STRIDE + k8;
            uint32_t d0 = smem_u32(basep + so);
            cpasync16(d0,                g_Xh  + gA);
            cpasync16(d0 + MATH * 2,     g_X2h + gA);
            cpasync16(d0 + 2 * MATH * 2, g_Wm  + gW);
            cpasync16(d0 + 3 * MATH * 2, g_Wv  + gW);
        }
    };

    const int NK = I_DIM / 32;
    load_stage(0, 0); CP_COMMIT();
    load_stage(1, 1); CP_COMMIT();

    for (int kt = 0; kt < NK; kt++) {
        asm volatile("cp.async.wait_group 1;\n" ::: "memory");
        __syncthreads();
        const int s = kt & 1;
        const __half* sX  = smem + (size_t)s * STAGEH;
        const __half* sX2 = sX + MATH;
        const __half* sWm = sX + 2 * MATH;
        const __half* sWv = sX + 3 * MATH;

#pragma unroll
        for (int ks = 0; ks < 2; ks++) {
            const int kb = ks * 16 + tg * 2;
            uint32_t ax[2][4], a2[2][4];
#pragma unroll
            for (int mt = 0; mt < 2; mt++) {
                const __half* p = sX + (wm_*32 + mt*16 + g) * SM_STRIDE + kb;
                ax[mt][0] = *(const uint32_t*)(p);
                ax[mt][1] = *(const uint32_t*)(p + 8 * SM_STRIDE);
                ax[mt][2] = *(const uint32_t*)(p + 8);
                ax[mt][3] = *(const uint32_t*)(p + 8 * SM_STRIDE + 8);
                const __half* q = sX2 + (wm_*32 + mt*16 + g) * SM_STRIDE + kb;
                a2[mt][0] = *(const uint32_t*)(q);
                a2[mt][1] = *(const uint32_t*)(q + 8 * SM_STRIDE);
                a2[mt][2] = *(const uint32_t*)(q + 8);
                a2[mt][3] = *(const uint32_t*)(q + 8 * SM_STRIDE + 8);
            }
            uint32_t bmf[8][2], bvf[8][2];
#pragma unroll
            for (int nt = 0; nt < 8; nt++) {
                const __half* p = sWm + (wn_*64 + nt*8 + g) * SM_STRIDE + kb;
                bmf[nt][0] = *(const uint32_t*)(p);
                bmf[nt][1] = *(const uint32_t*)(p + 8);
                const __half* q = sWv + (wn_*64 + nt*8 + g) * SM_STRIDE + kb;
                bvf[nt][0] = *(const uint32_t*)(q);
                bvf[nt][1] = *(const uint32_t*)(q + 8);
            }
#pragma unroll
            for (int mt = 0; mt < 2; mt++)
#pragma unroll
                for (int nt = 0; nt < 8; nt++) {
                    MMA16816(accm[mt][nt], ax[mt], bmf[nt]);
                    MMA16816(accv[mt][nt], a2[mt], bvf[nt]);
                }
        }
        __syncthreads();
        if (kt + 2 < NK) load_stage(s, kt + 2);
        CP_COMMIT();
    }

#pragma unroll
    for (int mt = 0; mt < 2; mt++)
#pragma unroll
        for (int nt = 0; nt < 8; nt++) {
            int colg = bn * 128 + wn_ * 64 + nt * 8 + tg * 2;
#pragma unroll
            for (int h = 0; h < 2; h++) {
                int rowg = bm * 128 + wm_ * 32 + mt * 16 + g + h * 8;
                size_t off = (size_t)rowg * O_DIM + colg;
                float2 e = *(const float2*)(eps + off);
                float v0 = accv[mt][nt][2*h];
                float v1 = accv[mt][nt][2*h + 1];
                float2 o;
                o.x = accm[mt][nt][2*h]     + sqrtf(fmaxf(v0, 1e-8f)) * e.x;
                o.y = accm[mt][nt][2*h + 1] + sqrtf(fmaxf(v1, 1e-8f)) * e.y;
                *(float2*)(out + off) = o;
            }
        }
}

extern "C" void kernel_launch(void* const* d_in, const int* in_sizes, int n_in,
                              void* d_out, int out_size) {
    const float* x   = (const float*)d_in[0];
    const float* tn  = (const float*)d_in[1];
    const float* tp  = (const float*)d_in[2];
    const float* sc  = (const float*)d_in[3];
    const float* eps = (const float*)d_in[4];
    float* out = (float*)d_out;

    probe_kernel<<<1, 1>>>();

    const int n4x = B_DIM * I_DIM / 4;
    prep_x_kernel<<<n4x / 256, 256>>>((const float4*)x, n4x);

    const int n4w = O_DIM * I_DIM / 4;
    prep_w_kernel<<<n4w / 256, 256>>>((const float4*)tn, (const float4*)tp,
                                      (const float4*)sc, n4w);

    cudaFuncSetAttribute(lrnet_tc_kernel,
                         cudaFuncAttributeMaxDynamicSharedMemorySize, TC_SMEM);
    dim3 tgrid(2, O_DIM / TILE_N, B_DIM / 256);
    lrnet_tc_kernel<<<tgrid, TC_THREADS, TC_SMEM>>>(eps, out);

    cudaFuncSetAttribute(lrnet_gemm_kernel,
                         cudaFuncAttributeMaxDynamicSharedMemorySize, FB_SMEM);
    dim3 fgrid(O_DIM / 128, B_DIM / 128);
    lrnet_gemm_kernel<<<fgrid, 256, FB_SMEM>>>(eps, out);
}

// round 7
// speedup vs baseline: 1.3115x; 1.3115x over previous
#include <cuda_runtime.h>
#include <cuda_fp16.h>
#include <stdint.h>

#define O_DIM 4096
#define I_DIM 4096
#define B_DIM 4096

#if defined(__CUDA_ARCH_SPECIFIC__) || defined(__CUDA_ARCH_FEAT_SM103_ALL) || defined(__CUDA_ARCH_FEAT_SM100_ALL)
#define HAS_TC 1
#else
#define HAS_TC 0
#endif

// -------- scratch (static device globals; allocation-free) --------
__device__ __half g_Xh [(size_t)B_DIM * I_DIM];
__device__ __half g_X2h[(size_t)B_DIM * I_DIM];   // used by fallback path only
__device__ __half g_Wm [(size_t)O_DIM * I_DIM];
__device__ __half g_Wv [(size_t)O_DIM * I_DIM];
__device__ int    g_use_tc;

__global__ void probe_kernel() {
#if HAS_TC
    g_use_tc = 1;
#else
    g_use_tc = 0;
#endif
}

// -------- prep kernels (HBM-bound) --------
__global__ void prep_x_kernel(const float4* __restrict__ x, int n4) {
    int i = blockIdx.x * blockDim.x + threadIdx.x;
    if (i >= n4) return;
    float4 v = x[i];
    __half2* xh = reinterpret_cast<__half2*>(g_Xh);
    __half2* x2 = reinterpret_cast<__half2*>(g_X2h);
    xh[2*i]   = __floats2half2_rn(v.x, v.y);
    xh[2*i+1] = __floats2half2_rn(v.z, v.w);
    x2[2*i]   = __floats2half2_rn(v.x*v.x, v.y*v.y);
    x2[2*i+1] = __floats2half2_rn(v.z*v.z, v.w*v.w);
}

__global__ void prep_w_kernel(const float4* __restrict__ tn4,
                              const float4* __restrict__ tp4,
                              const float4* __restrict__ sc4, int n4) {
    int i = blockIdx.x * blockDim.x + threadIdx.x;
    if (i >= n4) return;
    float4 a = tn4[i], b = tp4[i], s = sc4[i];
    const float* ap = &a.x;
    const float* bp = &b.x;
    const float* sp = &s.x;
    float wm[4], wv[4];
#pragma unroll
    for (int c = 0; c < 4; c++) {
        float t_n = ap[c], t_p = bp[c], sc = sp[c];
        float m  = fmaxf(fmaxf(t_n, t_p), 0.0f);
        float en = __expf(t_n - m);
        float ez = __expf(-m);
        float ep = __expf(t_p - m);
        float inv = 1.0f / (en + ez + ep);
        float pn = en * inv, pp = ep * inv;
        float d  = pp - pn;
        wm[c] = d * sc;
        wv[c] = (pp + pn - d * d) * sc * sc;
    }
    __half2* wmh = reinterpret_cast<__half2*>(g_Wm);
    __half2* wvh = reinterpret_cast<__half2*>(g_Wv);
    wmh[2*i]   = __floats2half2_rn(wm[0], wm[1]);
    wmh[2*i+1] = __floats2half2_rn(wm[2], wm[3]);
    wvh[2*i]   = __floats2half2_rn(wv[0], wv[1]);
    wvh[2*i+1] = __floats2half2_rn(wv[2], wv[3]);
}

// ======================= common helpers =======================
__device__ __forceinline__ uint32_t smem_u32(const void* p) {
    uint32_t a;
    asm("{ .reg .u64 t; cvta.to.shared.u64 t, %1; cvt.u32.u64 %0, t; }"
        : "=r"(a) : "l"(p));
    return a;
}
__device__ __forceinline__ uint32_t swz(uint32_t o) { return o ^ ((o >> 3) & 0x70); }

__device__ __forceinline__ void cpasync16(uint32_t d, const void* s) {
    asm volatile("cp.async.cg.shared.global [%0], [%1], 16;\n" :: "r"(d), "l"(s));
}
#define CP_COMMIT() asm volatile("cp.async.commit_group;\n" ::: "memory")

__device__ __forceinline__ void lds128(uint32_t& a, uint32_t& b, uint32_t& c,
                                       uint32_t& d, uint32_t addr) {
    asm volatile("ld.shared.v4.u32 {%0,%1,%2,%3}, [%4];"
                 : "=r"(a), "=r"(b), "=r"(c), "=r"(d) : "r"(addr));
}
__device__ __forceinline__ void sts128(uint32_t addr, uint32_t a, uint32_t b,
                                       uint32_t c, uint32_t d) {
    asm volatile("st.shared.v4.b32 [%0], {%1,%2,%3,%4};"
                 :: "r"(addr), "r"(a), "r"(b), "r"(c), "r"(d));
}
__device__ __forceinline__ uint32_t sqh2(uint32_t v) {
    __half2 h = *reinterpret_cast<__half2*>(&v);
    h = __hmul2(h, h);
    return *reinterpret_cast<uint32_t*>(&h);
}

// ======================= cg2 tcgen05 dual-GEMM, warp-specialized =======================
// X2 tile computed in smem from X (warps 0-1, software-pipelined); only X, Wm, Wv hit L2.
#define TILE_MH 128
#define TILE_N  256
#define KB      64
#define SX      0
#define SX2     16384
#define SWM     32768
#define SWV     49152
#define STAGE_BYTES 65536
#define NSTAGE  3
#define TC_SMEM (NSTAGE * STAGE_BYTES + 1024)
#define TC_THREADS 160

#define MMA_IDESC ((1u << 4) | ((TILE_N / 8) << 17) | ((256 / 16) << 24))

#if HAS_TC
__device__ __forceinline__ uint64_t make_desc(uint32_t addr) {
    const uint64_t base =
        (uint64_t(2) << 61) | (uint64_t(1) << 46) |
        (uint64_t(64) << 32) | (uint64_t(1) << 16);
    return base | ((uint64_t)(addr >> 4) & 0x3FFF);
}

__device__ __forceinline__ void mma_f16_ss_cg2(uint32_t d_tmem, uint64_t a_desc,
                                               uint64_t b_desc, uint32_t idesc,
                                               uint32_t acc) {
    asm volatile(
        "{\n\t.reg .pred p;\n\t"
        "setp.ne.u32 p, %5, 0;\n\t"
        "tcgen05.mma.cta_group::2.kind::f16 [%0], %1, %2, %3, "
        "{%4, %4, %4, %4, %4, %4, %4, %4}, p;\n\t"
        "}"
        :: "r"(d_tmem), "l"(a_desc), "l"(b_desc), "r"(idesc), "r"(0u), "r"(acc)
        : "memory");
}

__device__ __forceinline__ void mbar_wait(uint32_t mbar, uint32_t parity) {
    asm volatile(
        "{\n\t.reg .pred P;\n\t"
        "WL_%=:\n\t"
        "mbarrier.try_wait.parity.acquire.cta.shared::cta.b64 P, [%0], %1, 0x989680;\n\t"
        "@P bra.uni WD_%=;\n\t"
        "bra.uni WL_%=;\n\t"
        "WD_%=:\n\t}"
        :: "r"(mbar), "r"(parity) : "memory");
}

__device__ __forceinline__ void mbar_arrive_rank(uint32_t local_addr, uint32_t rank) {
    asm volatile(
        "{\n\t.reg .b32 r;\n\t"
        "mapa.shared::cluster.u32 r, %0, %1;\n\t"
        "mbarrier.arrive.shared::cluster.b64 _, [r];\n\t"
        "}"
        :: "r"(local_addr), "r"(rank) : "memory");
}

#define MBAR_ARRIVE(mbar) \
    asm volatile("mbarrier.arrive.release.cta.shared::cta.b64 _, [%0];" :: "r"(mbar) : "memory")

#define CP_MBAR_ARRIVE_NOINC(mbar) \
    asm volatile("cp.async.mbarrier.arrive.noinc.shared::cta.b64 [%0];" \
                 :: "r"(mbar) : "memory")

#define TC_COMMIT_MC2(mbar) \
    asm volatile("tcgen05.commit.cta_group::2.mbarrier::arrive::one.shared::cluster.multicast::cluster.b64 [%0], %1;" \
                 :: "r"(mbar), "h"((uint16_t)3) : "memory")

#define TC_LD_X32(r, ta) \
    asm volatile( \
        "tcgen05.ld.sync.aligned.32x32b.x32.b32 " \
        "{%0, %1, %2, %3, %4, %5, %6, %7, %8, %9, %10, %11, %12, %13, %14, %15, " \
        " %16, %17, %18, %19, %20, %21, %22, %23, %24, %25, %26, %27, %28, %29, %30, %31}, [%32];" \
        : "=r"((r)[0]),  "=r"((r)[1]),  "=r"((r)[2]),  "=r"((r)[3]), \
          "=r"((r)[4]),  "=r"((r)[5]),  "=r"((r)[6]),  "=r"((r)[7]), \
          "=r"((r)[8]),  "=r"((r)[9]),  "=r"((r)[10]), "=r"((r)[11]), \
          "=r"((r)[12]), "=r"((r)[13]), "=r"((r)[14]), "=r"((r)[15]), \
          "=r"((r)[16]), "=r"((r)[17]), "=r"((r)[18]), "=r"((r)[19]), \
          "=r"((r)[20]), "=r"((r)[21]), "=r"((r)[22]), "=r"((r)[23]), \
          "=r"((r)[24]), "=r"((r)[25]), "=r"((r)[26]), "=r"((r)[27]), \
          "=r"((r)[28]), "=r"((r)[29]), "=r"((r)[30]), "=r"((r)[31]) \
        : "r"(ta))

#define CLUSTER_SYNC() do { \
    asm volatile("barrier.cluster.arrive.aligned;" ::: "memory"); \
    asm volatile("barrier.cluster.wait.aligned;" ::: "memory"); \
} while (0)
#endif  // HAS_TC

__global__ __launch_bounds__(TC_THREADS, 1) __cluster_dims__(2, 1, 1)
void lrnet_tc_kernel(const float* __restrict__ eps, float* __restrict__ out) {
#if HAS_TC
    extern __shared__ char dsm_raw[];
    // full[s] counts: leader 129 (64 X-thread arrives + 64 W cp-noinc + 1 peer fwd),
    //                 peer   128 (64 + 64).
    __shared__ __align__(16) unsigned long long s_full[NSTAGE];
    __shared__ __align__(16) unsigned long long s_done[NSTAGE];
    __shared__ uint32_t s_tmem;

    const int tid  = threadIdx.x;
    const int wid  = tid >> 5;
    const int lane = tid & 31;
    const int rank = blockIdx.x;
    const int bn   = blockIdx.y;
    const int bm   = blockIdx.z;

    uint32_t dyn  = smem_u32(dsm_raw);
    uint32_t base = (dyn + 1023u) & ~1023u;
    uint32_t fullA[NSTAGE], doneA[NSTAGE];
#pragma unroll
    for (int s = 0; s < NSTAGE; s++) {
        fullA[s] = smem_u32(&s_full[s]);
        doneA[s] = smem_u32(&s_done[s]);
    }

    if (wid == 0) {
        uint32_t slot = smem_u32(&s_tmem);
        asm volatile("tcgen05.alloc.cta_group::2.sync.aligned.shared::cta.b32 [%0], %1;"
                     :: "r"(slot), "r"(512u) : "memory");
        asm volatile("tcgen05.relinquish_alloc_permit.cta_group::2.sync.aligned;");
    }
    if (tid == 0) {
        const uint32_t fcnt = (rank == 0) ? 129u : 128u;
#pragma unroll
        for (int s = 0; s < NSTAGE; s++) {
            asm volatile("mbarrier.init.shared.b64 [%0], %1;" :: "r"(fullA[s]), "r"(fcnt) : "memory");
            asm volatile("mbarrier.init.shared.b64 [%0], %1;" :: "r"(doneA[s]), "r"(1u)   : "memory");
        }
    }
    __syncthreads();
    CLUSTER_SYNC();
    const uint32_t tmem = s_tmem;
    const int NK = I_DIM / KB;   // 64

    if (tid < 64) {
        // ---- X producer + squarer: warps 0-1, software-pipelined ----
        const size_t mrow0 = (size_t)bm * 256 + (size_t)rank * TILE_MH;

        auto issue_x = [&](int kt) {
            uint32_t sb = base + (uint32_t)(kt % NSTAGE) * STAGE_BYTES;
            size_t k0 = (size_t)kt * KB;
#pragma unroll
            for (int i = 0; i < 16; i++) {
                int idx = tid + i * 64;
                int row = idx >> 3, c = idx & 7;
                uint32_t off = swz((uint32_t)(row * 128 + c * 16));
                cpasync16(sb + SX + off, g_Xh + (mrow0 + row) * I_DIM + k0 + c * 8);
            }
            CP_COMMIT();
        };

        issue_x(0);   // prologue: stage 0 loads in flight
        for (int kt = 0; kt < NK; kt++) {
            const int s = kt % NSTAGE;
            if (kt + 1 < NK) {
                const int s1 = (kt + 1) % NSTAGE;
                if (kt + 1 >= NSTAGE)
                    mbar_wait(doneA[s1], (uint32_t)(((kt + 1 - NSTAGE) / NSTAGE) & 1));
                issue_x(kt + 1);                                   // overlap next stage
                asm volatile("cp.async.wait_group 1;\n" ::: "memory");  // stage kt resident
            } else {
                asm volatile("cp.async.wait_group 0;\n" ::: "memory");
            }
            // square stage kt (each thread squares exactly its own chunks)
            uint32_t sb = base + (uint32_t)s * STAGE_BYTES;
#pragma unroll
            for (int i = 0; i < 16; i++) {
                int idx = tid + i * 64;
                int row = idx >> 3, c = idx & 7;
                uint32_t off = swz((uint32_t)(row * 128 + c * 16));
                uint32_t a0, a1, a2, a3;
                lds128(a0, a1, a2, a3, sb + SX + off);
                sts128(sb + SX2 + off, sqh2(a0), sqh2(a1), sqh2(a2), sqh2(a3));
            }
            asm volatile("fence.proxy.async.shared::cta;\n" ::: "memory");
            MBAR_ARRIVE(fullA[s]);
        }
    } else if (tid < 128) {
        // ------------- W producer: warps 2-3 (free-running) -------------
        const int t = tid - 64;
        const size_t nrow0 = (size_t)bn * TILE_N + (size_t)rank * 128;
        for (int kt = 0; kt < NK; kt++) {
            const int s = kt % NSTAGE;
            if (kt >= NSTAGE)
                mbar_wait(doneA[s], (uint32_t)(((kt - NSTAGE) / NSTAGE) & 1));
            uint32_t sb = base + (uint32_t)s * STAGE_BYTES;
            size_t k0 = (size_t)kt * KB;
#pragma unroll
            for (int i = 0; i < 16; i++) {
                int idx = t + i * 64;
                int row = idx >> 3, c = idx & 7;
                uint32_t off = swz((uint32_t)(row * 128 + c * 16));
                size_t gW = (nrow0 + row) * I_DIM + k0 + c * 8;
                cpasync16(sb + SWM + off, g_Wm + gW);
                cpasync16(sb + SWV + off, g_Wv + gW);
            }
            CP_MBAR_ARRIVE_NOINC(fullA[s]);
        }
    } else if (tid == 128) {
        if (rank == 0) {
            // ------------- MMA issuer (leader) -------------
            for (int kt = 0; kt < NK; kt++) {
                const int s = kt % NSTAGE;
                const uint32_t ph = (uint32_t)((kt / NSTAGE) & 1);
                mbar_wait(fullA[s], ph);
                asm volatile("fence.proxy.async.shared::cta;\n" ::: "memory");
                uint32_t sb = base + (uint32_t)s * STAGE_BYTES;
                uint64_t dx  = make_desc(sb + SX);
                uint64_t dx2 = make_desc(sb + SX2);
                uint64_t dwm = make_desc(sb + SWM);
                uint64_t dwv = make_desc(sb + SWV);
#pragma unroll
                for (int k = 0; k < 4; k++) {
                    uint32_t acc = (kt > 0 || k > 0) ? 1u : 0u;
                    mma_f16_ss_cg2(tmem,       dx  + k * 2, dwm + k * 2, MMA_IDESC, acc);
                    mma_f16_ss_cg2(tmem + 256, dx2 + k * 2, dwv + k * 2, MMA_IDESC, acc);
                }
                TC_COMMIT_MC2(doneA[s]);
            }
        } else {
            // ------------- full -> leader forwarder (peer) -------------
            for (int kt = 0; kt < NK; kt++) {
                const int s = kt % NSTAGE;
                const uint32_t ph = (uint32_t)((kt / NSTAGE) & 1);
                mbar_wait(fullA[s], ph);
                asm volatile("fence.proxy.async.shared::cta;\n" ::: "memory");
                mbar_arrive_rank(fullA[s], 0);
            }
        }
    }

    // ---- wait for final stage's MMAs, then fused epilogue ----
    if (tid < 128) {
        mbar_wait(doneA[(NK - 1) % NSTAGE], (uint32_t)(((NK - 1) / NSTAGE) & 1));
        asm volatile("tcgen05.fence::after_thread_sync;" ::: "memory");

        const size_t orow = (size_t)bm * 256 + (size_t)rank * TILE_MH + wid * 32 + lane;
#pragma unroll 1
        for (int c = 0; c < TILE_N / 32; c++) {
            uint32_t mu[32], va[32];
            TC_LD_X32(mu, tmem + c * 32);
            TC_LD_X32(va, tmem + 256 + c * 32);
            asm volatile("tcgen05.wait::ld.sync.aligned;" ::: "memory");
            size_t colb = (size_t)bn * TILE_N + c * 32;
            const float4* ep = (const float4*)(eps + orow * O_DIM + colb);
            float4*       op = (float4*)(out + orow * O_DIM + colb);
#pragma unroll
            for (int j = 0; j < 8; j++) {
                float4 e = ep[j];
                float4 o;
                o.x = __uint_as_float(mu[4*j+0]) + sqrtf(fmaxf(__uint_as_float(va[4*j+0]), 1e-8f)) * e.x;
                o.y = __uint_as_float(mu[4*j+1]) + sqrtf(fmaxf(__uint_as_float(va[4*j+1]), 1e-8f)) * e.y;
                o.z = __uint_as_float(mu[4*j+2]) + sqrtf(fmaxf(__uint_as_float(va[4*j+2]), 1e-8f)) * e.z;
                o.w = __uint_as_float(mu[4*j+3]) + sqrtf(fmaxf(__uint_as_float(va[4*j+3]), 1e-8f)) * e.w;
                op[j] = o;
            }
        }
        asm volatile("tcgen05.fence::before_thread_sync;" ::: "memory");
    }

    __syncthreads();
    if (wid == 0) {
        asm volatile("tcgen05.dealloc.cta_group::2.sync.aligned.b32 %0, %1;"
                     :: "r"(tmem), "r"(512u));
    }
    CLUSTER_SYNC();
#endif  // HAS_TC
}

// ======================= mma.sync fallback (plain sm_103) =======================
#define SM_STRIDE 40
#define MATH (128 * SM_STRIDE)
#define STAGEH (4 * MATH)
#define FB_SMEM (2 * STAGEH * (int)sizeof(__half))

#define MMA16816(dd, aa, bb) \
    asm volatile("mma.sync.aligned.m16n8k16.row.col.f32.f16.f16.f32 " \
                 "{%0,%1,%2,%3},{%4,%5,%6,%7},{%8,%9},{%0,%1,%2,%3};\n" \
                 : "+f"(dd[0]), "+f"(dd[1]), "+f"(dd[2]), "+f"(dd[3]) \
                 : "r"(aa[0]), "r"(aa[1]), "r"(aa[2]), "r"(aa[3]), \
                   "r"(bb[0]), "r"(bb[1]))

__global__ __launch_bounds__(256, 1)
void lrnet_gemm_kernel(const float* __restrict__ eps, float* __restrict__ out) {
    if (g_use_tc) return;
    extern __shared__ __half smem[];
    const int tid  = threadIdx.x;
    const int lane = tid & 31;
    const int wid  = tid >> 5;
    const int g    = lane >> 2;
    const int tg   = lane & 3;
    const int wm_  = wid & 3;
    const int wn_  = wid >> 2;
    const int bm   = blockIdx.y;
    const int bn   = blockIdx.x;

    float accm[2][8][4];
    float accv[2][8][4];
#pragma unroll
    for (int mt = 0; mt < 2; mt++)
#pragma unroll
        for (int nt = 0; nt < 8; nt++)
#pragma unroll
            for (int r = 0; r < 4; r++) { accm[mt][nt][r] = 0.f; accv[mt][nt][r] = 0.f; }

    const int row0A = bm * 128;
    const int row0W = bn * 128;

    auto load_stage = [&](int s, int kt) {
        const size_t k0 = (size_t)kt * 32;
        __half* basep = smem + (size_t)s * STAGEH;
#pragma unroll
        for (int c = 0; c < 2; c++) {
            int idx = tid + c * 256;
            int row = idx >> 2;
            int k8  = (idx & 3) * 8;
            size_t gA = (size_t)(row0A + row) * I_DIM + k0 + k8;
            size_t gW = (size_t)(row0W + row) * I_DIM + k0 + k8;
            int so = row * SM_STRIDE + k8;
            uint32_t d0 = smem_u32(basep + so);
            cpasync16(d0,                g_Xh  + gA);
            cpasync16(d0 + MATH * 2,     g_X2h + gA);
            cpasync16(d0 + 2 * MATH * 2, g_Wm  + gW);
            cpasync16(d0 + 3 * MATH * 2, g_Wv  + gW);
        }
    };

    const int NK = I_DIM / 32;
    load_stage(0, 0); CP_COMMIT();
    load_stage(1, 1); CP_COMMIT();

    for (int kt = 0; kt < NK; kt++) {
        asm volatile("cp.async.wait_group 1;\n" ::: "memory");
        __syncthreads();
        const int s = kt & 1;
        const __half* sX  = smem + (size_t)s * STAGEH;
        const __half* sX2 = sX + MATH;
        const __half* sWm = sX + 2 * MATH;
        const __half* sWv = sX + 3 * MATH;

#pragma unroll
        for (int ks = 0; ks < 2; ks++) {
            const int kb = ks * 16 + tg * 2;
            uint32_t ax[2][4], a2[2][4];
#pragma unroll
            for (int mt = 0; mt < 2; mt++) {
                const __half* p = sX + (wm_*32 + mt*16 + g) * SM_STRIDE + kb;
                ax[mt][0] = *(const uint32_t*)(p);
                ax[mt][1] = *(const uint32_t*)(p + 8 * SM_STRIDE);
                ax[mt][2] = *(const uint32_t*)(p + 8);
                ax[mt][3] = *(const uint32_t*)(p + 8 * SM_STRIDE + 8);
                const __half* q = sX2 + (wm_*32 + mt*16 + g) * SM_STRIDE + kb;
                a2[mt][0] = *(const uint32_t*)(q);
                a2[mt][1] = *(const uint32_t*)(q + 8 * SM_STRIDE);
                a2[mt][2] = *(const uint32_t*)(q + 8);
                a2[mt][3] = *(const uint32_t*)(q + 8 * SM_STRIDE + 8);
            }
            uint32_t bmf[8][2], bvf[8][2];
#pragma unroll
            for (int nt = 0; nt < 8; nt++) {
                const __half* p = sWm + (wn_*64 + nt*8 + g) * SM_STRIDE + kb;
                bmf[nt][0] = *(const uint32_t*)(p);
                bmf[nt][1] = *(const uint32_t*)(p + 8);
                const __half* q = sWv + (wn_*64 + nt*8 + g) * SM_STRIDE + kb;
                bvf[nt][0] = *(const uint32_t*)(q);
                bvf[nt][1] = *(const uint32_t*)(q + 8);
            }
#pragma unroll
            for (int mt = 0; mt < 2; mt++)
#pragma unroll
                for (int nt = 0; nt < 8; nt++) {
                    MMA16816(accm[mt][nt], ax[mt], bmf[nt]);
                    MMA16816(accv[mt][nt], a2[mt], bvf[nt]);
                }
        }
        __syncthreads();
        if (kt + 2 < NK) load_stage(s, kt + 2);
        CP_COMMIT();
    }

#pragma unroll
    for (int mt = 0; mt < 2; mt++)
#pragma unroll
        for (int nt = 0; nt < 8; nt++) {
            int colg = bn * 128 + wn_ * 64 + nt * 8 + tg * 2;
#pragma unroll
            for (int h = 0; h < 2; h++) {
                int rowg = bm * 128 + wm_ * 32 + mt * 16 + g + h * 8;
                size_t off = (size_t)rowg * O_DIM + colg;
                float2 e = *(const float2*)(eps + off);
                float v0 = accv[mt][nt][2*h];
                float v1 = accv[mt][nt][2*h + 1];
                float2 o;
                o.x = accm[mt][nt][2*h]     + sqrtf(fmaxf(v0, 1e-8f)) * e.x;
                o.y = accm[mt][nt][2*h + 1] + sqrtf(fmaxf(v1, 1e-8f)) * e.y;
                *(float2*)(out + off) = o;
            }
        }
}

extern "C" void kernel_launch(void* const* d_in, const int* in_sizes, int n_in,
                              void* d_out, int out_size) {
    const float* x   = (const float*)d_in[0];
    const float* tn  = (const float*)d_in[1];
    const float* tp  = (const float*)d_in[2];
    const float* sc  = (const float*)d_in[3];
    const float* eps = (const float*)d_in[4];
    float* out = (float*)d_out;

    probe_kernel<<<1, 1>>>();

    const int n4x = B_DIM * I_DIM / 4;
    prep_x_kernel<<<n4x / 256, 256>>>((const float4*)x, n4x);

    const int n4w = O_DIM * I_DIM / 4;
    prep_w_kernel<<<n4w / 256, 256>>>((const float4*)tn, (const float4*)tp,
                                      (const float4*)sc, n4w);

    cudaFuncSetAttribute(lrnet_tc_kernel,
                         cudaFuncAttributeMaxDynamicSharedMemorySize, TC_SMEM);
    dim3 tgrid(2, O_DIM / TILE_N, B_DIM / 256);
    lrnet_tc_kernel<<<tgrid, TC_THREADS, TC_SMEM>>>(eps, out);

    cudaFuncSetAttribute(lrnet_gemm_kernel,
                         cudaFuncAttributeMaxDynamicSharedMemorySize, FB_SMEM);
    dim3 fgrid(O_DIM / 128, B_DIM / 128);
    lrnet_gemm_kernel<<<fgrid, 256, FB_SMEM>>>(eps, out);
}

// round 9
// speedup vs baseline: 1.5716x; 1.1983x over previous
#include <cuda_runtime.h>
#include <cuda_fp16.h>
#include <stdint.h>

#define O_DIM 4096
#define I_DIM 4096
#define B_DIM 4096

#if defined(__CUDA_ARCH_SPECIFIC__) || defined(__CUDA_ARCH_FEAT_SM103_ALL) || defined(__CUDA_ARCH_FEAT_SM100_ALL)
#define HAS_TC 1
#else
#define HAS_TC 0
#endif

// -------- scratch (static device globals; allocation-free) --------
__device__ __half g_Xh [(size_t)B_DIM * I_DIM];
__device__ __half g_X2h[(size_t)B_DIM * I_DIM];
__device__ __half g_Wm [(size_t)O_DIM * I_DIM];
__device__ __half g_Wv [(size_t)O_DIM * I_DIM];
__device__ int    g_use_tc;

__global__ void probe_kernel() {
#if HAS_TC
    g_use_tc = 1;
#else
    g_use_tc = 0;
#endif
}

// -------- prep kernels (HBM-bound) --------
__global__ void prep_x_kernel(const float4* __restrict__ x, int n4) {
    int i = blockIdx.x * blockDim.x + threadIdx.x;
    if (i >= n4) return;
    float4 v = x[i];
    __half2* xh = reinterpret_cast<__half2*>(g_Xh);
    __half2* x2 = reinterpret_cast<__half2*>(g_X2h);
    xh[2*i]   = __floats2half2_rn(v.x, v.y);
    xh[2*i+1] = __floats2half2_rn(v.z, v.w);
    x2[2*i]   = __floats2half2_rn(v.x*v.x, v.y*v.y);
    x2[2*i+1] = __floats2half2_rn(v.z*v.z, v.w*v.w);
}

__global__ void prep_w_kernel(const float4* __restrict__ tn4,
                              const float4* __restrict__ tp4,
                              const float4* __restrict__ sc4, int n4) {
    int i = blockIdx.x * blockDim.x + threadIdx.x;
    if (i >= n4) return;
    float4 a = tn4[i], b = tp4[i], s = sc4[i];
    const float* ap = &a.x;
    const float* bp = &b.x;
    const float* sp = &s.x;
    float wm[4], wv[4];
#pragma unroll
    for (int c = 0; c < 4; c++) {
        float t_n = ap[c], t_p = bp[c], sc = sp[c];
        float m  = fmaxf(fmaxf(t_n, t_p), 0.0f);
        float en = __expf(t_n - m);
        float ez = __expf(-m);
        float ep = __expf(t_p - m);
        float inv = 1.0f / (en + ez + ep);
        float pn = en * inv, pp = ep * inv;
        float d  = pp - pn;
        wm[c] = d * sc;
        wv[c] = (pp + pn - d * d) * sc * sc;
    }
    __half2* wmh = reinterpret_cast<__half2*>(g_Wm);
    __half2* wvh = reinterpret_cast<__half2*>(g_Wv);
    wmh[2*i]   = __floats2half2_rn(wm[0], wm[1]);
    wmh[2*i+1] = __floats2half2_rn(wm[2], wm[3]);
    wvh[2*i]   = __floats2half2_rn(wv[0], wv[1]);
    wvh[2*i+1] = __floats2half2_rn(wv[2], wv[3]);
}

// ======================= common helpers =======================
__device__ __forceinline__ uint32_t smem_u32(const void* p) {
    uint32_t a;
    asm("{ .reg .u64 t; cvta.to.shared.u64 t, %1; cvt.u32.u64 %0, t; }"
        : "=r"(a) : "l"(p));
    return a;
}
__device__ __forceinline__ uint32_t swz(uint32_t o) { return o ^ ((o >> 3) & 0x70); }

__device__ __forceinline__ void cpasync16(uint32_t d, const void* s) {
    asm volatile("cp.async.cg.shared.global [%0], [%1], 16;\n" :: "r"(d), "l"(s));
}
#define CP_COMMIT() asm volatile("cp.async.commit_group;\n" ::: "memory")

// ======================= cg2 tcgen05 dual-pipe dual-GEMM (single issuer) =======================
//   pipe-mu : X  tile (16KB) + Wm tile (16KB), TMEM cols [0,256)
//   pipe-va : X2 tile (16KB) + Wv tile (16KB), TMEM cols [256,512)
// Each pipe: 3 stages x 32KB, own full/done barriers. ONE issuer thread
// (leader tid 128) alternates between pipes — cg2 MMA issue stays single-thread.
#define TILE_MH 128
#define TILE_N  256
#define KB      64
#define PIPE_STAGE 32768
#define NSTAGE  3
#define VA_BASE (NSTAGE * PIPE_STAGE)             // 98304
#define TC_SMEM (2 * NSTAGE * PIPE_STAGE + 1024)  // 197632
#define TC_THREADS 160

#define MMA_IDESC ((1u << 4) | ((TILE_N / 8) << 17) | ((256 / 16) << 24))

#if HAS_TC
__device__ __forceinline__ uint64_t make_desc(uint32_t addr) {
    const uint64_t base =
        (uint64_t(2) << 61) | (uint64_t(1) << 46) |
        (uint64_t(64) << 32) | (uint64_t(1) << 16);
    return base | ((uint64_t)(addr >> 4) & 0x3FFF);
}

__device__ __forceinline__ void mma_f16_ss_cg2(uint32_t d_tmem, uint64_t a_desc,
                                               uint64_t b_desc, uint32_t idesc,
                                               uint32_t acc) {
    asm volatile(
        "{\n\t.reg .pred p;\n\t"
        "setp.ne.u32 p, %5, 0;\n\t"
        "tcgen05.mma.cta_group::2.kind::f16 [%0], %1, %2, %3, "
        "{%4, %4, %4, %4, %4, %4, %4, %4}, p;\n\t"
        "}"
        :: "r"(d_tmem), "l"(a_desc), "l"(b_desc), "r"(idesc), "r"(0u), "r"(acc)
        : "memory");
}

__device__ __forceinline__ void mbar_wait(uint32_t mbar, uint32_t parity) {
    asm volatile(
        "{\n\t.reg .pred P;\n\t"
        "WL_%=:\n\t"
        "mbarrier.try_wait.parity.acquire.cta.shared::cta.b64 P, [%0], %1, 0x989680;\n\t"
        "@P bra.uni WD_%=;\n\t"
        "bra.uni WL_%=;\n\t"
        "WD_%=:\n\t}"
        :: "r"(mbar), "r"(parity) : "memory");
}

__device__ __forceinline__ void mbar_arrive_rank(uint32_t local_addr, uint32_t rank) {
    asm volatile(
        "{\n\t.reg .b32 r;\n\t"
        "mapa.shared::cluster.u32 r, %0, %1;\n\t"
        "mbarrier.arrive.shared::cluster.b64 _, [r];\n\t"
        "}"
        :: "r"(local_addr), "r"(rank) : "memory");
}

#define CP_MBAR_ARRIVE_NOINC(mbar) \
    asm volatile("cp.async.mbarrier.arrive.noinc.shared::cta.b64 [%0];" \
                 :: "r"(mbar) : "memory")

#define TC_COMMIT_MC2(mbar) \
    asm volatile("tcgen05.commit.cta_group::2.mbarrier::arrive::one.shared::cluster.multicast::cluster.b64 [%0], %1;" \
                 :: "r"(mbar), "h"((uint16_t)3) : "memory")

#define TC_LD_X32(r, ta) \
    asm volatile( \
        "tcgen05.ld.sync.aligned.32x32b.x32.b32 " \
        "{%0, %1, %2, %3, %4, %5, %6, %7, %8, %9, %10, %11, %12, %13, %14, %15, " \
        " %16, %17, %18, %19, %20, %21, %22, %23, %24, %25, %26, %27, %28, %29, %30, %31}, [%32];" \
        : "=r"((r)[0]),  "=r"((r)[1]),  "=r"((r)[2]),  "=r"((r)[3]), \
          "=r"((r)[4]),  "=r"((r)[5]),  "=r"((r)[6]),  "=r"((r)[7]), \
          "=r"((r)[8]),  "=r"((r)[9]),  "=r"((r)[10]), "=r"((r)[11]), \
          "=r"((r)[12]), "=r"((r)[13]), "=r"((r)[14]), "=r"((r)[15]), \
          "=r"((r)[16]), "=r"((r)[17]), "=r"((r)[18]), "=r"((r)[19]), \
          "=r"((r)[20]), "=r"((r)[21]), "=r"((r)[22]), "=r"((r)[23]), \
          "=r"((r)[24]), "=r"((r)[25]), "=r"((r)[26]), "=r"((r)[27]), \
          "=r"((r)[28]), "=r"((r)[29]), "=r"((r)[30]), "=r"((r)[31]) \
        : "r"(ta))

#define CLUSTER_SYNC() do { \
    asm volatile("barrier.cluster.arrive.aligned;" ::: "memory"); \
    asm volatile("barrier.cluster.wait.aligned;" ::: "memory"); \
} while (0)
#endif  // HAS_TC

__global__ __launch_bounds__(TC_THREADS, 1) __cluster_dims__(2, 1, 1)
void lrnet_tc_kernel(const float* __restrict__ eps, float* __restrict__ out) {
#if HAS_TC
    extern __shared__ char dsm_raw[];
    // full counts: leader 65 (64 producer cp-noinc + 1 peer fwd); peer 64.
    __shared__ __align__(16) unsigned long long s_full_mu[NSTAGE];
    __shared__ __align__(16) unsigned long long s_done_mu[NSTAGE];
    __shared__ __align__(16) unsigned long long s_full_va[NSTAGE];
    __shared__ __align__(16) unsigned long long s_done_va[NSTAGE];
    __shared__ uint32_t s_tmem;

    const int tid  = threadIdx.x;
    const int wid  = tid >> 5;
    const int lane = tid & 31;
    const int rank = blockIdx.x;
    const int bn   = blockIdx.y;
    const int bm   = blockIdx.z;

    uint32_t dyn  = smem_u32(dsm_raw);
    uint32_t base = (dyn + 1023u) & ~1023u;
    uint32_t fMu[NSTAGE], dMu[NSTAGE], fVa[NSTAGE], dVa[NSTAGE];
#pragma unroll
    for (int s = 0; s < NSTAGE; s++) {
        fMu[s] = smem_u32(&s_full_mu[s]);
        dMu[s] = smem_u32(&s_done_mu[s]);
        fVa[s] = smem_u32(&s_full_va[s]);
        dVa[s] = smem_u32(&s_done_va[s]);
    }

    if (wid == 0) {
        uint32_t slot = smem_u32(&s_tmem);
        asm volatile("tcgen05.alloc.cta_group::2.sync.aligned.shared::cta.b32 [%0], %1;"
                     :: "r"(slot), "r"(512u) : "memory");
        asm volatile("tcgen05.relinquish_alloc_permit.cta_group::2.sync.aligned;");
    }
    if (tid == 0) {
        const uint32_t fcnt = (rank == 0) ? 65u : 64u;
#pragma unroll
        for (int s = 0; s < NSTAGE; s++) {
            asm volatile("mbarrier.init.shared.b64 [%0], %1;" :: "r"(fMu[s]), "r"(fcnt) : "memory");
            asm volatile("mbarrier.init.shared.b64 [%0], %1;" :: "r"(dMu[s]), "r"(1u)   : "memory");
            asm volatile("mbarrier.init.shared.b64 [%0], %1;" :: "r"(fVa[s]), "r"(fcnt) : "memory");
            asm volatile("mbarrier.init.shared.b64 [%0], %1;" :: "r"(dVa[s]), "r"(1u)   : "memory");
        }
    }
    __syncthreads();
    CLUSTER_SYNC();
    const uint32_t tmem = s_tmem;
    const int NK = I_DIM / KB;   // 64

    const size_t mrow0 = (size_t)bm * 256 + (size_t)rank * TILE_MH;
    const size_t nrow0 = (size_t)bn * TILE_N + (size_t)rank * 128;

    if (tid < 64) {
        // ---------- pipe-mu producer: X + Wm (warps 0-1) ----------
        for (int kt = 0; kt < NK; kt++) {
            const int s = kt % NSTAGE;
            if (kt >= NSTAGE)
                mbar_wait(dMu[s], (uint32_t)(((kt - NSTAGE) / NSTAGE) & 1));
            uint32_t sb = base + (uint32_t)s * PIPE_STAGE;
            size_t k0 = (size_t)kt * KB;
#pragma unroll
            for (int i = 0; i < 16; i++) {
                int idx = tid + i * 64;
                int row = idx >> 3, c = idx & 7;
                uint32_t off = swz((uint32_t)(row * 128 + c * 16));
                cpasync16(sb + off,         g_Xh + (mrow0 + row) * I_DIM + k0 + c * 8);
                cpasync16(sb + 16384 + off, g_Wm + (nrow0 + row) * I_DIM + k0 + c * 8);
            }
            CP_MBAR_ARRIVE_NOINC(fMu[s]);
        }
    } else if (tid < 128) {
        // ---------- pipe-va producer: X2 + Wv (warps 2-3) ----------
        const int t = tid - 64;
        for (int kt = 0; kt < NK; kt++) {
            const int s = kt % NSTAGE;
            if (kt >= NSTAGE)
                mbar_wait(dVa[s], (uint32_t)(((kt - NSTAGE) / NSTAGE) & 1));
            uint32_t sb = base + VA_BASE + (uint32_t)s * PIPE_STAGE;
            size_t k0 = (size_t)kt * KB;
#pragma unroll
            for (int i = 0; i < 16; i++) {
                int idx = t + i * 64;
                int row = idx >> 3, c = idx & 7;
                uint32_t off = swz((uint32_t)(row * 128 + c * 16));
                cpasync16(sb + off,         g_X2h + (mrow0 + row) * I_DIM + k0 + c * 8);
                cpasync16(sb + 16384 + off, g_Wv  + (nrow0 + row) * I_DIM + k0 + c * 8);
            }
            CP_MBAR_ARRIVE_NOINC(fVa[s]);
        }
    } else if (tid == 128) {
        // ---------- SINGLE issuer (leader) / forwarder (peer), both pipes ----------
        if (rank == 0) {
            for (int kt = 0; kt < NK; kt++) {
                const int s = kt % NSTAGE;
                const uint32_t ph = (uint32_t)((kt / NSTAGE) & 1);

                // pipe-mu half-stage
                mbar_wait(fMu[s], ph);
                asm volatile("fence.proxy.async.shared::cta;\n" ::: "memory");
                {
                    uint32_t sb = base + (uint32_t)s * PIPE_STAGE;
                    uint64_t dx  = make_desc(sb);
                    uint64_t dwm = make_desc(sb + 16384);
#pragma unroll
                    for (int k = 0; k < 4; k++)
                        mma_f16_ss_cg2(tmem, dx + k * 2, dwm + k * 2, MMA_IDESC,
                                       (kt > 0 || k > 0) ? 1u : 0u);
                    TC_COMMIT_MC2(dMu[s]);
                }

                // pipe-va half-stage (wait overlaps queued mu MMAs)
                mbar_wait(fVa[s], ph);
                asm volatile("fence.proxy.async.shared::cta;\n" ::: "memory");
                {
                    uint32_t sb = base + VA_BASE + (uint32_t)s * PIPE_STAGE;
                    uint64_t dx2 = make_desc(sb);
                    uint64_t dwv = make_desc(sb + 16384);
#pragma unroll
                    for (int k = 0; k < 4; k++)
                        mma_f16_ss_cg2(tmem + 256, dx2 + k * 2, dwv + k * 2, MMA_IDESC,
                                       (kt > 0 || k > 0) ? 1u : 0u);
                    TC_COMMIT_MC2(dVa[s]);
                }
            }
        } else {
            for (int kt = 0; kt < NK; kt++) {
                const int s = kt % NSTAGE;
                const uint32_t ph = (uint32_t)((kt / NSTAGE) & 1);
                mbar_wait(fMu[s], ph);
                asm volatile("fence.proxy.async.shared::cta;\n" ::: "memory");
                mbar_arrive_rank(fMu[s], 0);
                mbar_wait(fVa[s], ph);
                asm volatile("fence.proxy.async.shared::cta;\n" ::: "memory");
                mbar_arrive_rank(fVa[s], 0);
            }
        }
    }

    // ---- wait for both pipes' final MMAs, then fused epilogue ----
    if (tid < 128) {
        const int lk = NK - 1;
        const uint32_t lph = (uint32_t)((lk / NSTAGE) & 1);
        mbar_wait(dMu[lk % NSTAGE], lph);
        mbar_wait(dVa[lk % NSTAGE], lph);
        asm volatile("tcgen05.fence::after_thread_sync;" ::: "memory");

        const size_t orow = (size_t)bm * 256 + (size_t)rank * TILE_MH + wid * 32 + lane;
#pragma unroll 1
        for (int c = 0; c < TILE_N / 32; c++) {
            uint32_t mu[32], va[32];
            TC_LD_X32(mu, tmem + c * 32);
            TC_LD_X32(va, tmem + 256 + c * 32);
            asm volatile("tcgen05.wait::ld.sync.aligned;" ::: "memory");
            size_t colb = (size_t)bn * TILE_N + c * 32;
            const float4* ep = (const float4*)(eps + orow * O_DIM + colb);
            float4*       op = (float4*)(out + orow * O_DIM + colb);
#pragma unroll
            for (int j = 0; j < 8; j++) {
                float4 e = ep[j];
                float4 o;
                o.x = __uint_as_float(mu[4*j+0]) + sqrtf(fmaxf(__uint_as_float(va[4*j+0]), 1e-8f)) * e.x;
                o.y = __uint_as_float(mu[4*j+1]) + sqrtf(fmaxf(__uint_as_float(va[4*j+1]), 1e-8f)) * e.y;
                o.z = __uint_as_float(mu[4*j+2]) + sqrtf(fmaxf(__uint_as_float(va[4*j+2]), 1e-8f)) * e.z;
                o.w = __uint_as_float(mu[4*j+3]) + sqrtf(fmaxf(__uint_as_float(va[4*j+3]), 1e-8f)) * e.w;
                op[j] = o;
            }
        }
        asm volatile("tcgen05.fence::before_thread_sync;" ::: "memory");
    }

    __syncthreads();
    if (wid == 0) {
        asm volatile("tcgen05.dealloc.cta_group::2.sync.aligned.b32 %0, %1;"
                     :: "r"(tmem), "r"(512u));
    }
    CLUSTER_SYNC();
#endif  // HAS_TC
}

// ======================= mma.sync fallback (plain sm_103) =======================
#define SM_STRIDE 40
#define MATH (128 * SM_STRIDE)
#define STAGEH (4 * MATH)
#define FB_SMEM (2 * STAGEH * (int)sizeof(__half))

#define MMA16816(dd, aa, bb) \
    asm volatile("mma.sync.aligned.m16n8k16.row.col.f32.f16.f16.f32 " \
                 "{%0,%1,%2,%3},{%4,%5,%6,%7},{%8,%9},{%0,%1,%2,%3};\n" \
                 : "+f"(dd[0]), "+f"(dd[1]), "+f"(dd[2]), "+f"(dd[3]) \
                 : "r"(aa[0]), "r"(aa[1]), "r"(aa[2]), "r"(aa[3]), \
                   "r"(bb[0]), "r"(bb[1]))

__global__ __launch_bounds__(256, 1)
void lrnet_gemm_kernel(const float* __restrict__ eps, float* __restrict__ out) {
    if (g_use_tc) return;
    extern __shared__ __half smem[];
    const int tid  = threadIdx.x;
    const int lane = tid & 31;
    const int wid  = tid >> 5;
    const int g    = lane >> 2;
    const int tg   = lane & 3;
    const int wm_  = wid & 3;
    const int wn_  = wid >> 2;
    const int bm   = blockIdx.y;
    const int bn   = blockIdx.x;

    float accm[2][8][4];
    float accv[2][8][4];
#pragma unroll
    for (int mt = 0; mt < 2; mt++)
#pragma unroll
        for (int nt = 0; nt < 8; nt++)
#pragma unroll
            for (int r = 0; r < 4; r++) { accm[mt][nt][r] = 0.f; accv[mt][nt][r] = 0.f; }

    const int row0A = bm * 128;
    const int row0W = bn * 128;

    auto load_stage = [&](int s, int kt) {
        const size_t k0 = (size_t)kt * 32;
        __half* basep = smem + (size_t)s * STAGEH;
#pragma unroll
        for (int c = 0; c < 2; c++) {
            int idx = tid + c * 256;
            int row = idx >> 2;
            int k8  = (idx & 3) * 8;
            size_t gA = (size_t)(row0A + row) * I_DIM + k0 + k8;
            size_t gW = (size_t)(row0W + row) * I_DIM + k0 + k8;
            int so = row * SM_STRIDE + k8;
            uint32_t d0 = smem_u32(basep + so);
            cpasync16(d0,                g_Xh  + gA);
            cpasync16(d0 + MATH * 2,     g_X2h + gA);
            cpasync16(d0 + 2 * MATH * 2, g_Wm  + gW);
            cpasync16(d0 + 3 * MATH * 2, g_Wv  + gW);
        }
    };

    const int NK = I_DIM / 32;
    load_stage(0, 0); CP_COMMIT();
    load_stage(1, 1); CP_COMMIT();

    for (int kt = 0; kt < NK; kt++) {
        asm volatile("cp.async.wait_group 1;\n" ::: "memory");
        __syncthreads();
        const int s = kt & 1;
        const __half* sX  = smem + (size_t)s * STAGEH;
        const __half* sX2 = sX + MATH;
        const __half* sWm = sX + 2 * MATH;
        const __half* sWv = sX + 3 * MATH;

#pragma unroll
        for (int ks = 0; ks < 2; ks++) {
            const int kb = ks * 16 + tg * 2;
            uint32_t ax[2][4], a2[2][4];
#pragma unroll
            for (int mt = 0; mt < 2; mt++) {
                const __half* p = sX + (wm_*32 + mt*16 + g) * SM_STRIDE + kb;
                ax[mt][0] = *(const uint32_t*)(p);
                ax[mt][1] = *(const uint32_t*)(p + 8 * SM_STRIDE);
                ax[mt][2] = *(const uint32_t*)(p + 8);
                ax[mt][3] = *(const uint32_t*)(p + 8 * SM_STRIDE + 8);
                const __half* q = sX2 + (wm_*32 + mt*16 + g) * SM_STRIDE + kb;
                a2[mt][0] = *(const uint32_t*)(q);
                a2[mt][1] = *(const uint32_t*)(q + 8 * SM_STRIDE);
                a2[mt][2] = *(const uint32_t*)(q + 8);
                a2[mt][3] = *(const uint32_t*)(q + 8 * SM_STRIDE + 8);
            }
            uint32_t bmf[8][2], bvf[8][2];
#pragma unroll
            for (int nt = 0; nt < 8; nt++) {
                const __half* p = sWm + (wn_*64 + nt*8 + g) * SM_STRIDE + kb;
                bmf[nt][0] = *(const uint32_t*)(p);
                bmf[nt][1] = *(const uint32_t*)(p + 8);
                const __half* q = sWv + (wn_*64 + nt*8 + g) * SM_STRIDE + kb;
                bvf[nt][0] = *(const uint32_t*)(q);
                bvf[nt][1] = *(const uint32_t*)(q + 8);
            }
#pragma unroll
            for (int mt = 0; mt < 2; mt++)
#pragma unroll
                for (int nt = 0; nt < 8; nt++) {
                    MMA16816(accm[mt][nt], ax[mt], bmf[nt]);
                    MMA16816(accv[mt][nt], a2[mt], bvf[nt]);
                }
        }
        __syncthreads();
        if (kt + 2 < NK) load_stage(s, kt + 2);
        CP_COMMIT();
    }

#pragma unroll
    for (int mt = 0; mt < 2; mt++)
#pragma unroll
        for (int nt = 0; nt < 8; nt++) {
            int colg = bn * 128 + wn_ * 64 + nt * 8 + tg * 2;
#pragma unroll
            for (int h = 0; h < 2; h++) {
                int rowg = bm * 128 + wm_ * 32 + mt * 16 + g + h * 8;
                size_t off = (size_t)rowg * O_DIM + colg;
                float2 e = *(const float2*)(eps + off);
                float v0 = accv[mt][nt][2*h];
                float v1 = accv[mt][nt][2*h + 1];
                float2 o;
                o.x = accm[mt][nt][2*h]     + sqrtf(fmaxf(v0, 1e-8f)) * e.x;
                o.y = accm[mt][nt][2*h + 1] + sqrtf(fmaxf(v1, 1e-8f)) * e.y;
                *(float2*)(out + off) = o;
            }
        }
}

extern "C" void kernel_launch(void* const* d_in, const int* in_sizes, int n_in,
                              void* d_out, int out_size) {
    const float* x   = (const float*)d_in[0];
    const float* tn  = (const float*)d_in[1];
    const float* tp  = (const float*)d_in[2];
    const float* sc  = (const float*)d_in[3];
    const float* eps = (const float*)d_in[4];
    float* out = (float*)d_out;

    probe_kernel<<<1, 1>>>();

    const int n4x = B_DIM * I_DIM / 4;
    prep_x_kernel<<<n4x / 256, 256>>>((const float4*)x, n4x);

    const int n4w = O_DIM * I_DIM / 4;
    prep_w_kernel<<<n4w / 256, 256>>>((const float4*)tn, (const float4*)tp,
                                      (const float4*)sc, n4w);

    cudaFuncSetAttribute(lrnet_tc_kernel,
                         cudaFuncAttributeMaxDynamicSharedMemorySize, TC_SMEM);
    dim3 tgrid(2, O_DIM / TILE_N, B_DIM / 256);
    lrnet_tc_kernel<<<tgrid, TC_THREADS, TC_SMEM>>>(eps, out);

    cudaFuncSetAttribute(lrnet_gemm_kernel,
                         cudaFuncAttributeMaxDynamicSharedMemorySize, FB_SMEM);
    dim3 fgrid(O_DIM / 128, B_DIM / 128);
    lrnet_gemm_kernel<<<fgrid, 256, FB_SMEM>>>(eps, out);
}